// round 1
// baseline (speedup 1.0000x reference)
#include <cuda_runtime.h>
#include <math.h>

#define BSZ 2
#define LSEQ 2048
#define DMODEL 1024
#define DINNER 2048
#define NSTATE 16
#define ROWS (BSZ*LSEQ)   /* 4096 */

/* ------------------------------------------------------------------ */
/* Scratch (static __device__ globals; allocation-free per harness)   */
/* ------------------------------------------------------------------ */
__device__ float g_h   [(size_t)ROWS*DMODEL];     /* post-LN            */
__device__ float g_xg  [(size_t)ROWS*2*DINNER];   /* h @ W_in           */
__device__ float g_xs  [(size_t)ROWS*DINNER];     /* conv+silu          */
__device__ float g_delta[ROWS];                   /* row sums -> delta  */
__device__ float g_dA  [(size_t)ROWS*NSTATE];
__device__ float g_Bx  [(size_t)ROWS*NSTATE];
__device__ float g_hs  [(size_t)ROWS*NSTATE];
__device__ float g_y   [(size_t)ROWS*DINNER];     /* pre-W_out          */

/* ------------------------------------------------------------------ */
/* LayerNorm: one block per row of 1024                               */
/* ------------------------------------------------------------------ */
__global__ void ln_kernel(const float* __restrict__ x,
                          const float* __restrict__ gamma,
                          const float* __restrict__ beta)
{
    int row = blockIdx.x;
    int tx  = threadIdx.x;                       /* 256 threads */
    const float4* xr = (const float4*)(x + (size_t)row*DMODEL);
    float4 v = xr[tx];
    float s  = v.x + v.y + v.z + v.w;
    float ss = v.x*v.x + v.y*v.y + v.z*v.z + v.w*v.w;
    #pragma unroll
    for (int o = 16; o; o >>= 1) {
        s  += __shfl_down_sync(0xffffffffu, s,  o);
        ss += __shfl_down_sync(0xffffffffu, ss, o);
    }
    __shared__ float sh[8], sh2[8];
    int w = tx >> 5, l = tx & 31;
    if (l == 0) { sh[w] = s; sh2[w] = ss; }
    __syncthreads();
    if (tx == 0) {
        float S = 0.f, SS = 0.f;
        #pragma unroll
        for (int i = 0; i < 8; i++) { S += sh[i]; SS += sh2[i]; }
        sh[0]  = S  * (1.0f/DMODEL);
        sh2[0] = SS * (1.0f/DMODEL);
    }
    __syncthreads();
    float mean = sh[0];
    float var  = sh2[0] - mean*mean;
    float r    = rsqrtf(var + 1e-5f);
    float4 gg = ((const float4*)gamma)[tx];
    float4 bb = ((const float4*)beta )[tx];
    float4 o;
    o.x = (v.x - mean)*r*gg.x + bb.x;
    o.y = (v.y - mean)*r*gg.y + bb.y;
    o.z = (v.z - mean)*r*gg.z + bb.z;
    o.w = (v.w - mean)*r*gg.w + bb.w;
    ((float4*)(g_h + (size_t)row*DMODEL))[tx] = o;
}

__global__ void zero_delta_kernel()
{
    int i = blockIdx.x*256 + threadIdx.x;
    if (i < ROWS) g_delta[i] = 0.f;
}

/* ------------------------------------------------------------------ */
/* Tiled SGEMM: C(MxN) = A(MxK) @ B(KxN), all row-major.              */
/* BM=BN=128, BK=16, 256 threads, 8x8 per thread.                     */
/* MODE 0: plain store                                                */
/* MODE 1: no store; rowsum[row] += sum_j softplus(acc+bias[col])     */
/* MODE 2: C = acc + resid                                            */
/* All of M,N,K are multiples of 128/16 here: no bounds checks.       */
/* ------------------------------------------------------------------ */
template<int MODE>
__global__ __launch_bounds__(256)
void sgemm_kernel(const float* __restrict__ A, const float* __restrict__ B,
                  float* __restrict__ C, int M, int N, int Kd,
                  const float* __restrict__ bias,
                  float* __restrict__ rowsum,
                  const float* __restrict__ resid)
{
    __shared__ float As[16][128];
    __shared__ float Bs[16][128];

    int tid  = threadIdx.x;
    int row0 = blockIdx.y * 128;
    int col0 = blockIdx.x * 128;
    int ty = tid >> 4;          /* 0..15 -> rows ty*8..ty*8+7 */
    int tx = tid & 15;          /* 0..15 -> cols tx*8..tx*8+7 */

    int aRow = tid >> 2;        /* 0..63  (+64)  */
    int aK4  = tid & 3;
    int bRow = tid >> 5;        /* 0..7   (+8)   */
    int bC4  = tid & 31;

    float acc[8][8];
    #pragma unroll
    for (int i = 0; i < 8; i++)
        #pragma unroll
        for (int j = 0; j < 8; j++) acc[i][j] = 0.f;

    for (int kt = 0; kt < Kd; kt += 16) {
        #pragma unroll
        for (int h = 0; h < 2; h++) {
            int r = aRow + h*64;
            float4 va = *(const float4*)(A + (size_t)(row0 + r)*Kd + kt + aK4*4);
            As[aK4*4+0][r] = va.x;
            As[aK4*4+1][r] = va.y;
            As[aK4*4+2][r] = va.z;
            As[aK4*4+3][r] = va.w;
        }
        #pragma unroll
        for (int h = 0; h < 2; h++) {
            int r = bRow + h*8;
            float4 vb = *(const float4*)(B + (size_t)(kt + r)*N + col0 + bC4*4);
            *(float4*)&Bs[r][bC4*4] = vb;
        }
        __syncthreads();
        #pragma unroll
        for (int k = 0; k < 16; k++) {
            float ra[8], rb[8];
            #pragma unroll
            for (int i = 0; i < 8; i++) ra[i] = As[k][ty*8 + i];
            #pragma unroll
            for (int j = 0; j < 8; j++) rb[j] = Bs[k][tx*8 + j];
            #pragma unroll
            for (int i = 0; i < 8; i++)
                #pragma unroll
                for (int j = 0; j < 8; j++)
                    acc[i][j] += ra[i] * rb[j];
        }
        __syncthreads();
    }

    if (MODE == 1) {
        /* softplus + row-sum reduction into rowsum (delta accumulator) */
        float rs[8];
        #pragma unroll
        for (int i = 0; i < 8; i++) {
            float s = 0.f;
            #pragma unroll
            for (int j = 0; j < 8; j++) {
                float z = acc[i][j] + bias[col0 + tx*8 + j];
                s += (z > 20.f) ? z : log1pf(__expf(z));
            }
            rs[i] = s;
        }
        float* red = &As[0][0];         /* reuse smem: 128 floats */
        if (tid < 128) red[tid] = 0.f;
        __syncthreads();
        #pragma unroll
        for (int i = 0; i < 8; i++)
            atomicAdd(&red[ty*8 + i], rs[i]);
        __syncthreads();
        if (tid < 128)
            atomicAdd(&rowsum[row0 + tid], red[tid]);
    } else {
        #pragma unroll
        for (int i = 0; i < 8; i++) {
            int row = row0 + ty*8 + i;
            #pragma unroll
            for (int j4 = 0; j4 < 2; j4++) {
                int col = col0 + tx*8 + j4*4;
                float4 o;
                o.x = acc[i][j4*4+0];
                o.y = acc[i][j4*4+1];
                o.z = acc[i][j4*4+2];
                o.w = acc[i][j4*4+3];
                if (MODE == 2) {
                    float4 rr = *(const float4*)(resid + (size_t)row*N + col);
                    o.x += rr.x; o.y += rr.y; o.z += rr.z; o.w += rr.w;
                }
                *(float4*)(C + (size_t)row*N + col) = o;
            }
        }
    }
}

/* ------------------------------------------------------------------ */
/* Depthwise causal conv (K=4) + bias + SiLU.                         */
/* Reads xs half of g_xg, writes g_xs. One thread per channel d,      */
/* looping over a chunk of L (coalesced across d within a warp).      */
/* ------------------------------------------------------------------ */
#define CONV_CH 64
__global__ void conv_silu_kernel(const float* __restrict__ conv_w,
                                 const float* __restrict__ conv_b)
{
    int d  = blockIdx.x*256 + threadIdx.x;    /* 0..2047 */
    int b  = blockIdx.z;
    int l0 = blockIdx.y * CONV_CH;

    float4 w4 = *(const float4*)(conv_w + d*4);  /* w[0..3] */
    float cb  = conv_b[d];

    const float* xgp = g_xg;                  /* (b,l, 0..2047) half */
    float p1 = (l0 >= 1) ? xgp[((size_t)(b*LSEQ + l0-1))*(2*DINNER) + d] : 0.f;
    float p2 = (l0 >= 2) ? xgp[((size_t)(b*LSEQ + l0-2))*(2*DINNER) + d] : 0.f;
    float p3 = (l0 >= 3) ? xgp[((size_t)(b*LSEQ + l0-3))*(2*DINNER) + d] : 0.f;

    for (int i = 0; i < CONV_CH; i++) {
        int l = l0 + i;
        float cur = xgp[((size_t)(b*LSEQ + l))*(2*DINNER) + d];
        /* out[l] = w0*x[l-3] + w1*x[l-2] + w2*x[l-1] + w3*x[l] + cb */
        float v = w4.x*p3 + w4.y*p2 + w4.z*p1 + w4.w*cur + cb;
        float s = v / (1.f + __expf(-v));     /* silu */
        g_xs[((size_t)(b*LSEQ + l))*DINNER + d] = s;
        p3 = p2; p2 = p1; p1 = cur;
    }
}

/* ------------------------------------------------------------------ */
/* Bx + dA: Bx[row,n] = delta * sum_d xs[row,d]*B_mat[n,d]            */
/*          dA[row,n] = exp(delta * (-exp(A_log[n])))                 */
/* One block per row, 128 threads.                                    */
/* ------------------------------------------------------------------ */
__global__ void bxda_kernel(const float* __restrict__ B_mat,
                            const float* __restrict__ A_log)
{
    int row = blockIdx.x;
    int tx  = threadIdx.x;      /* 128 */
    float sums[NSTATE];
    #pragma unroll
    for (int n = 0; n < NSTATE; n++) sums[n] = 0.f;

    const float* xr = g_xs + (size_t)row*DINNER;
    for (int d = tx; d < DINNER; d += 128) {
        float xv = xr[d];
        #pragma unroll
        for (int n = 0; n < NSTATE; n++)
            sums[n] += xv * B_mat[n*DINNER + d];
    }
    #pragma unroll
    for (int n = 0; n < NSTATE; n++)
        #pragma unroll
        for (int o = 16; o; o >>= 1)
            sums[n] += __shfl_down_sync(0xffffffffu, sums[n], o);

    __shared__ float sh[4][NSTATE];
    int w = tx >> 5, l = tx & 31;
    if (l == 0) {
        #pragma unroll
        for (int n = 0; n < NSTATE; n++) sh[w][n] = sums[n];
    }
    __syncthreads();
    if (tx < NSTATE) {
        float tot   = sh[0][tx] + sh[1][tx] + sh[2][tx] + sh[3][tx];
        float delta = g_delta[row] * (1.0f/DINNER);
        float An    = -__expf(A_log[tx]);
        g_Bx[row*NSTATE + tx] = tot * delta;
        g_dA[row*NSTATE + tx] = __expf(delta * An);
    }
}

/* ------------------------------------------------------------------ */
/* Parallel linear-recurrence scan (Hillis-Steele over affine maps).  */
/* One block per (b,n), 1024 threads, 2048 elements, ping-pong smem.  */
/* h_l = a_l*h_{l-1} + b_l ; compose (a,b) after (A,B) = (aA, aB+b)   */
/* ------------------------------------------------------------------ */
__global__ __launch_bounds__(1024)
void scan_kernel()
{
    __shared__ float Aa[2][LSEQ];
    __shared__ float Bb[2][LSEQ];
    int bn = blockIdx.x;
    int b  = bn >> 4;
    int n  = bn & 15;
    int tid = threadIdx.x;

    for (int l = tid; l < LSEQ; l += 1024) {
        size_t idx = ((size_t)(b*LSEQ + l))*NSTATE + n;
        Aa[0][l] = g_dA[idx];
        Bb[0][l] = g_Bx[idx];
    }
    __syncthreads();
    int src = 0;
    for (int off = 1; off < LSEQ; off <<= 1) {
        int dst = src ^ 1;
        for (int l = tid; l < LSEQ; l += 1024) {
            float a = Aa[src][l], bv = Bb[src][l];
            if (l >= off) {
                float ap = Aa[src][l-off], bp = Bb[src][l-off];
                Aa[dst][l] = a * ap;
                Bb[dst][l] = a * bp + bv;
            } else {
                Aa[dst][l] = a;
                Bb[dst][l] = bv;
            }
        }
        __syncthreads();
        src ^= 1;
    }
    for (int l = tid; l < LSEQ; l += 1024) {
        size_t idx = ((size_t)(b*LSEQ + l))*NSTATE + n;
        g_hs[idx] = Bb[src][l];
    }
}

/* ------------------------------------------------------------------ */
/* y = (hs @ C^T) + D*xs, then * silu(gate).  One block per row.      */
/* ------------------------------------------------------------------ */
__global__ void ymix_kernel(const float* __restrict__ C_mat,
                            const float* __restrict__ D_vec)
{
    int row = blockIdx.x;
    int tx  = threadIdx.x;      /* 256 */
    __shared__ float hrow[NSTATE];
    if (tx < NSTATE) hrow[tx] = g_hs[row*NSTATE + tx];
    __syncthreads();

    for (int d = tx; d < DINNER; d += 256) {
        const float4* c4 = (const float4*)(C_mat + (size_t)d*NSTATE);
        float acc = 0.f;
        #pragma unroll
        for (int q = 0; q < 4; q++) {
            float4 c = c4[q];
            acc += c.x*hrow[q*4+0] + c.y*hrow[q*4+1]
                 + c.z*hrow[q*4+2] + c.w*hrow[q*4+3];
        }
        float xv = g_xs[(size_t)row*DINNER + d];
        float gt = g_xg[(size_t)row*(2*DINNER) + DINNER + d];
        float sg = gt / (1.f + __expf(-gt));
        g_y[(size_t)row*DINNER + d] = (acc + D_vec[d]*xv) * sg;
    }
}

/* ------------------------------------------------------------------ */
extern "C" void kernel_launch(void* const* d_in, const int* in_sizes, int n_in,
                              void* d_out, int out_size)
{
    const float* x        = (const float*)d_in[0];
    const float* ln_gamma = (const float*)d_in[1];
    const float* ln_beta  = (const float*)d_in[2];
    const float* W_in     = (const float*)d_in[3];
    const float* conv_w   = (const float*)d_in[4];
    const float* conv_b   = (const float*)d_in[5];
    const float* A_log    = (const float*)d_in[6];
    const float* B_mat    = (const float*)d_in[7];
    const float* C_mat    = (const float*)d_in[8];
    const float* D_vec    = (const float*)d_in[9];
    const float* Wd       = (const float*)d_in[10];
    const float* bd       = (const float*)d_in[11];
    const float* W_out    = (const float*)d_in[12];
    float* out = (float*)d_out;

    float *p_h, *p_xg, *p_xs, *p_delta, *p_y;
    cudaGetSymbolAddress((void**)&p_h,     g_h);
    cudaGetSymbolAddress((void**)&p_xg,    g_xg);
    cudaGetSymbolAddress((void**)&p_xs,    g_xs);
    cudaGetSymbolAddress((void**)&p_delta, g_delta);
    cudaGetSymbolAddress((void**)&p_y,     g_y);

    /* 1. LayerNorm */
    ln_kernel<<<ROWS, 256>>>(x, ln_gamma, ln_beta);

    /* delta accumulator -> 0 (replayed every graph launch: deterministic) */
    zero_delta_kernel<<<(ROWS+255)/256, 256>>>();

    /* 2. xg = h @ W_in   (4096 x 1024 x 4096) */
    sgemm_kernel<0><<<dim3((2*DINNER)/128, ROWS/128), 256>>>(
        p_h, W_in, p_xg, ROWS, 2*DINNER, DMODEL, nullptr, nullptr, nullptr);

    /* 3. depthwise causal conv + SiLU */
    conv_silu_kernel<<<dim3(DINNER/256, LSEQ/CONV_CH, BSZ), 256>>>(conv_w, conv_b);

    /* 4. delta row-sums = sum softplus(xs @ Wd + bd)  (4096 x 2048 x 2048) */
    sgemm_kernel<1><<<dim3(DINNER/128, ROWS/128), 256>>>(
        p_xs, Wd, nullptr, ROWS, DINNER, DINNER, bd, p_delta, nullptr);

    /* 5. Bx, dA */
    bxda_kernel<<<ROWS, 128>>>(B_mat, A_log);

    /* 6. scan over L */
    scan_kernel<<<BSZ*NSTATE, 1024>>>();

    /* 7. y = (hs @ C^T + D*xs) * silu(gate) */
    ymix_kernel<<<ROWS, 256>>>(C_mat, D_vec);

    /* 8. out = y @ W_out + x   (4096 x 2048 x 1024) */
    sgemm_kernel<2><<<dim3(DMODEL/128, ROWS/128), 256>>>(
        p_y, W_out, out, ROWS, DMODEL, DINNER, nullptr, nullptr, x);
}

// round 3
// speedup vs baseline: 2.0287x; 2.0287x over previous
#include <cuda_runtime.h>
#include <math.h>
#include <stdint.h>

#define BSZ 2
#define LSEQ 2048
#define DMODEL 1024
#define DINNER 2048
#define NSTATE 16
#define ROWS (BSZ*LSEQ)   /* 4096 */

/* ------------------------------------------------------------------ */
/* Scratch (static __device__ globals; allocation-free per harness)   */
/* ------------------------------------------------------------------ */
__device__ float g_h   [(size_t)ROWS*DMODEL];     /* post-LN            */
__device__ float g_xg  [(size_t)ROWS*2*DINNER];   /* h @ W_in           */
__device__ float g_xs  [(size_t)ROWS*DINNER];     /* conv+silu          */
__device__ float g_delta[ROWS];                   /* row sums -> delta  */
__device__ float g_dA  [(size_t)ROWS*NSTATE];
__device__ float g_Bx  [(size_t)ROWS*NSTATE];
__device__ float g_hs  [(size_t)ROWS*NSTATE];
__device__ float g_y   [(size_t)ROWS*DINNER];     /* pre-W_out          */
__device__ float g_wt  [(size_t)4096*1024];       /* transposed weight (reused 3x) */

__device__ __forceinline__ uint32_t f2tf32(float v) {
    uint32_t o; asm("cvt.rna.tf32.f32 %0, %1;" : "=r"(o) : "f"(v)); return o;
}

/* ------------------------------------------------------------------ */
/* LayerNorm: one block per row of 1024                               */
/* ------------------------------------------------------------------ */
__global__ void ln_kernel(const float* __restrict__ x,
                          const float* __restrict__ gamma,
                          const float* __restrict__ beta)
{
    int row = blockIdx.x;
    int tx  = threadIdx.x;                       /* 256 threads */
    const float4* xr = (const float4*)(x + (size_t)row*DMODEL);
    float4 v = xr[tx];
    float s  = v.x + v.y + v.z + v.w;
    float ss = v.x*v.x + v.y*v.y + v.z*v.z + v.w*v.w;
    #pragma unroll
    for (int o = 16; o; o >>= 1) {
        s  += __shfl_down_sync(0xffffffffu, s,  o);
        ss += __shfl_down_sync(0xffffffffu, ss, o);
    }
    __shared__ float sh[8], sh2[8];
    int w = tx >> 5, l = tx & 31;
    if (l == 0) { sh[w] = s; sh2[w] = ss; }
    __syncthreads();
    if (tx == 0) {
        float S = 0.f, SS = 0.f;
        #pragma unroll
        for (int i = 0; i < 8; i++) { S += sh[i]; SS += sh2[i]; }
        sh[0]  = S  * (1.0f/DMODEL);
        sh2[0] = SS * (1.0f/DMODEL);
    }
    __syncthreads();
    float mean = sh[0];
    float var  = sh2[0] - mean*mean;
    float r    = rsqrtf(var + 1e-5f);
    float4 gg = ((const float4*)gamma)[tx];
    float4 bb = ((const float4*)beta )[tx];
    float4 o;
    o.x = (v.x - mean)*r*gg.x + bb.x;
    o.y = (v.y - mean)*r*gg.y + bb.y;
    o.z = (v.z - mean)*r*gg.z + bb.z;
    o.w = (v.w - mean)*r*gg.w + bb.w;
    ((float4*)(g_h + (size_t)row*DMODEL))[tx] = o;
}

__global__ void zero_delta_kernel()
{
    int i = blockIdx.x*256 + threadIdx.x;
    if (i < ROWS) g_delta[i] = 0.f;
}

/* ------------------------------------------------------------------ */
/* Transpose weight [K,N] fp32 -> [N,K] tf32-rounded fp32 container.  */
/* ------------------------------------------------------------------ */
__global__ void transpose_tf32_kernel(const float* __restrict__ W,
                                      float* __restrict__ Wt, int K, int N)
{
    __shared__ float tile[32][33];
    int n0 = blockIdx.x*32, k0 = blockIdx.y*32;
    int tx = threadIdx.x, ty = threadIdx.y;
    #pragma unroll
    for (int i = 0; i < 32; i += 8)
        tile[ty+i][tx] = W[(size_t)(k0+ty+i)*N + n0+tx];
    __syncthreads();
    #pragma unroll
    for (int i = 0; i < 32; i += 8) {
        uint32_t o = f2tf32(tile[tx][ty+i]);
        ((uint32_t*)Wt)[(size_t)(n0+ty+i)*K + k0+tx] = o;
    }
}

/* ------------------------------------------------------------------ */
/* tf32 mma.sync GEMM:  C(MxN) = A(MxK) @ Wt(NxK)^T                   */
/* CTA tile 128x128, BK=32, 256 threads = 8 warps, warp tile 64x32.   */
/* Each warp: 4x4 grid of m16n8k8 per k-step (4 ksteps per chunk).    */
/* MODE 0: plain store  MODE 1: rowsum += softplus(acc+bias)          */
/* MODE 2: C = acc + resid                                            */
/* smem: padded stride 36 floats -> conflict-free fragment LDS.       */
/* ------------------------------------------------------------------ */
#define SST 36                        /* smem row stride (floats) */
#define TILEF (128*SST)               /* floats per tile buffer   */
#define GSMEM_BYTES (4*TILEF*4)       /* A0,A1,B0,B1 */

__device__ __forceinline__ void mma_tf32(float* c, const uint32_t* a, const uint32_t* b)
{
    asm volatile(
        "mma.sync.aligned.m16n8k8.row.col.f32.tf32.tf32.f32 "
        "{%0,%1,%2,%3}, {%4,%5,%6,%7}, {%8,%9}, {%0,%1,%2,%3};"
        : "+f"(c[0]), "+f"(c[1]), "+f"(c[2]), "+f"(c[3])
        : "r"(a[0]), "r"(a[1]), "r"(a[2]), "r"(a[3]), "r"(b[0]), "r"(b[1]));
}

template<int MODE>
__global__ __launch_bounds__(256)
void mm_gemm_kernel(const float* __restrict__ A, const float* __restrict__ Bt,
                    float* __restrict__ C, int M, int N, int Kd,
                    const float* __restrict__ bias,
                    float* __restrict__ rowsum,
                    const float* __restrict__ resid)
{
    extern __shared__ float dsm[];
    float* Abuf[2] = { dsm,            dsm + TILEF   };
    float* Bbuf[2] = { dsm + 2*TILEF,  dsm + 3*TILEF };

    int tid  = threadIdx.x;
    int wid  = tid >> 5;
    int lane = tid & 31;
    int g    = lane >> 2;      /* fragment row group 0..7 */
    int q    = lane & 3;       /* quad lane 0..3          */
    int mwb  = (wid & 1) * 64; /* warp m-base within CTA  */
    int nwb  = (wid >> 1) * 32;/* warp n-base within CTA  */
    int row0 = blockIdx.y * 128;
    int col0 = blockIdx.x * 128;

    int r_ld  = tid >> 3;      /* 0..31 step: row per thread (x4 iters covers 128) */
    int c4_ld = tid & 7;       /* k-float4 index 0..7 */

    const float* Ab = A  + (size_t)row0*Kd;
    const float* Bb = Bt + (size_t)col0*Kd;

    float acc[4][4][4];
    #pragma unroll
    for (int mt = 0; mt < 4; mt++)
        #pragma unroll
        for (int nt = 0; nt < 4; nt++)
            #pragma unroll
            for (int j = 0; j < 4; j++) acc[mt][nt][j] = 0.f;

    const int nch = Kd >> 5;

    /* --- stage chunk 0 --- */
    #pragma unroll
    for (int i = 0; i < 4; i++) {
        int r = r_ld + 32*i;
        float4 v = *(const float4*)(Ab + (size_t)r*Kd + c4_ld*4);
        uint32_t* d = (uint32_t*)&Abuf[0][r*SST + c4_ld*4];
        d[0] = f2tf32(v.x); d[1] = f2tf32(v.y); d[2] = f2tf32(v.z); d[3] = f2tf32(v.w);
        float4 w = *(const float4*)(Bb + (size_t)r*Kd + c4_ld*4);
        *(float4*)&Bbuf[0][r*SST + c4_ld*4] = w;   /* already tf32-rounded */
    }
    __syncthreads();

    float4 pA[4], pB[4];
    for (int c = 0; c < nch; c++) {
        int cur = c & 1, nxt = cur ^ 1;
        bool more = (c + 1 < nch);
        if (more) {
            const float* An = Ab + (c+1)*32;
            const float* Bn = Bb + (c+1)*32;
            #pragma unroll
            for (int i = 0; i < 4; i++) {
                int r = r_ld + 32*i;
                pA[i] = *(const float4*)(An + (size_t)r*Kd + c4_ld*4);
                pB[i] = *(const float4*)(Bn + (size_t)r*Kd + c4_ld*4);
            }
        }

        /* --- compute on buffer cur --- */
        const uint32_t* As = (const uint32_t*)Abuf[cur];
        const uint32_t* Bs = (const uint32_t*)Bbuf[cur];
        #pragma unroll
        for (int ks = 0; ks < 4; ks++) {
            int k0 = ks * 8;
            uint32_t af[4][4], bf[4][2];
            #pragma unroll
            for (int mt = 0; mt < 4; mt++) {
                int r0 = mwb + mt*16 + g;
                af[mt][0] = As[(r0    )*SST + k0 + q    ];
                af[mt][1] = As[(r0 + 8)*SST + k0 + q    ];
                af[mt][2] = As[(r0    )*SST + k0 + q + 4];
                af[mt][3] = As[(r0 + 8)*SST + k0 + q + 4];
            }
            #pragma unroll
            for (int nt = 0; nt < 4; nt++) {
                int n0 = nwb + nt*8 + g;
                bf[nt][0] = Bs[n0*SST + k0 + q    ];
                bf[nt][1] = Bs[n0*SST + k0 + q + 4];
            }
            #pragma unroll
            for (int mt = 0; mt < 4; mt++)
                #pragma unroll
                for (int nt = 0; nt < 4; nt++)
                    mma_tf32(acc[mt][nt], af[mt], bf[nt]);
        }

        if (more) {
            #pragma unroll
            for (int i = 0; i < 4; i++) {
                int r = r_ld + 32*i;
                uint32_t* d = (uint32_t*)&Abuf[nxt][r*SST + c4_ld*4];
                d[0] = f2tf32(pA[i].x); d[1] = f2tf32(pA[i].y);
                d[2] = f2tf32(pA[i].z); d[3] = f2tf32(pA[i].w);
                *(float4*)&Bbuf[nxt][r*SST + c4_ld*4] = pB[i];
            }
        }
        __syncthreads();
    }

    /* --------------------------- epilogue -------------------------- */
    if (MODE == 1) {
        /* softplus + row-sum into rowsum */
        float part[4][2];
        #pragma unroll
        for (int mt = 0; mt < 4; mt++) {
            float s0 = 0.f, s1 = 0.f;
            #pragma unroll
            for (int nt = 0; nt < 4; nt++) {
                int colb = col0 + nwb + nt*8 + 2*q;
                float b0 = bias[colb], b1 = bias[colb+1];
                float z;
                z = acc[mt][nt][0] + b0; s0 += (z > 20.f) ? z : log1pf(__expf(z));
                z = acc[mt][nt][1] + b1; s0 += (z > 20.f) ? z : log1pf(__expf(z));
                z = acc[mt][nt][2] + b0; s1 += (z > 20.f) ? z : log1pf(__expf(z));
                z = acc[mt][nt][3] + b1; s1 += (z > 20.f) ? z : log1pf(__expf(z));
            }
            part[mt][0] = s0; part[mt][1] = s1;
        }
        float* red = dsm;     /* reuse smem (safe after last sync) */
        if (tid < 128) red[tid] = 0.f;
        __syncthreads();
        #pragma unroll
        for (int mt = 0; mt < 4; mt++) {
            atomicAdd(&red[mwb + mt*16 + g    ], part[mt][0]);
            atomicAdd(&red[mwb + mt*16 + g + 8], part[mt][1]);
        }
        __syncthreads();
        if (tid < 128)
            atomicAdd(&rowsum[row0 + tid], red[tid]);
    } else {
        #pragma unroll
        for (int mt = 0; mt < 4; mt++) {
            int r0 = row0 + mwb + mt*16 + g;
            #pragma unroll
            for (int nt = 0; nt < 4; nt++) {
                int col = col0 + nwb + nt*8 + 2*q;
                float2 o0 = make_float2(acc[mt][nt][0], acc[mt][nt][1]);
                float2 o1 = make_float2(acc[mt][nt][2], acc[mt][nt][3]);
                if (MODE == 2) {
                    float2 rr0 = *(const float2*)(resid + (size_t)r0*N + col);
                    float2 rr1 = *(const float2*)(resid + (size_t)(r0+8)*N + col);
                    o0.x += rr0.x; o0.y += rr0.y;
                    o1.x += rr1.x; o1.y += rr1.y;
                }
                *(float2*)(C + (size_t)r0*N + col)     = o0;
                *(float2*)(C + (size_t)(r0+8)*N + col) = o1;
            }
        }
    }
}

/* ------------------------------------------------------------------ */
/* Depthwise causal conv (K=4) + bias + SiLU.                         */
/* ------------------------------------------------------------------ */
#define CONV_CH 64
__global__ void conv_silu_kernel(const float* __restrict__ conv_w,
                                 const float* __restrict__ conv_b)
{
    int d  = blockIdx.x*256 + threadIdx.x;    /* 0..2047 */
    int b  = blockIdx.z;
    int l0 = blockIdx.y * CONV_CH;

    float4 w4 = *(const float4*)(conv_w + d*4);  /* w[0..3] */
    float cb  = conv_b[d];

    const float* xgp = g_xg;
    float p1 = (l0 >= 1) ? xgp[((size_t)(b*LSEQ + l0-1))*(2*DINNER) + d] : 0.f;
    float p2 = (l0 >= 2) ? xgp[((size_t)(b*LSEQ + l0-2))*(2*DINNER) + d] : 0.f;
    float p3 = (l0 >= 3) ? xgp[((size_t)(b*LSEQ + l0-3))*(2*DINNER) + d] : 0.f;

    for (int i = 0; i < CONV_CH; i++) {
        int l = l0 + i;
        float cur = xgp[((size_t)(b*LSEQ + l))*(2*DINNER) + d];
        float v = w4.x*p3 + w4.y*p2 + w4.z*p1 + w4.w*cur + cb;
        float s = v / (1.f + __expf(-v));     /* silu */
        g_xs[((size_t)(b*LSEQ + l))*DINNER + d] = s;
        p3 = p2; p2 = p1; p1 = cur;
    }
}

/* ------------------------------------------------------------------ */
/* Bx + dA                                                            */
/* ------------------------------------------------------------------ */
__global__ void bxda_kernel(const float* __restrict__ B_mat,
                            const float* __restrict__ A_log)
{
    int row = blockIdx.x;
    int tx  = threadIdx.x;      /* 128 */
    float sums[NSTATE];
    #pragma unroll
    for (int n = 0; n < NSTATE; n++) sums[n] = 0.f;

    const float* xr = g_xs + (size_t)row*DINNER;
    for (int d = tx; d < DINNER; d += 128) {
        float xv = xr[d];
        #pragma unroll
        for (int n = 0; n < NSTATE; n++)
            sums[n] += xv * B_mat[n*DINNER + d];
    }
    #pragma unroll
    for (int n = 0; n < NSTATE; n++)
        #pragma unroll
        for (int o = 16; o; o >>= 1)
            sums[n] += __shfl_down_sync(0xffffffffu, sums[n], o);

    __shared__ float sh[4][NSTATE];
    int w = tx >> 5, l = tx & 31;
    if (l == 0) {
        #pragma unroll
        for (int n = 0; n < NSTATE; n++) sh[w][n] = sums[n];
    }
    __syncthreads();
    if (tx < NSTATE) {
        float tot   = sh[0][tx] + sh[1][tx] + sh[2][tx] + sh[3][tx];
        float delta = g_delta[row] * (1.0f/DINNER);
        float An    = -__expf(A_log[tx]);
        g_Bx[row*NSTATE + tx] = tot * delta;
        g_dA[row*NSTATE + tx] = __expf(delta * An);
    }
}

/* ------------------------------------------------------------------ */
/* Parallel scan (Hillis-Steele over affine maps)                     */
/* ------------------------------------------------------------------ */
__global__ __launch_bounds__(1024)
void scan_kernel()
{
    __shared__ float Aa[2][LSEQ];
    __shared__ float Bb[2][LSEQ];
    int bn = blockIdx.x;
    int b  = bn >> 4;
    int n  = bn & 15;
    int tid = threadIdx.x;

    for (int l = tid; l < LSEQ; l += 1024) {
        size_t idx = ((size_t)(b*LSEQ + l))*NSTATE + n;
        Aa[0][l] = g_dA[idx];
        Bb[0][l] = g_Bx[idx];
    }
    __syncthreads();
    int src = 0;
    for (int off = 1; off < LSEQ; off <<= 1) {
        int dst = src ^ 1;
        for (int l = tid; l < LSEQ; l += 1024) {
            float a = Aa[src][l], bv = Bb[src][l];
            if (l >= off) {
                float ap = Aa[src][l-off], bp = Bb[src][l-off];
                Aa[dst][l] = a * ap;
                Bb[dst][l] = a * bp + bv;
            } else {
                Aa[dst][l] = a;
                Bb[dst][l] = bv;
            }
        }
        __syncthreads();
        src ^= 1;
    }
    for (int l = tid; l < LSEQ; l += 1024) {
        size_t idx = ((size_t)(b*LSEQ + l))*NSTATE + n;
        g_hs[idx] = Bb[src][l];
    }
}

/* ------------------------------------------------------------------ */
/* y = (hs @ C^T + D*xs) * silu(gate)                                 */
/* ------------------------------------------------------------------ */
__global__ void ymix_kernel(const float* __restrict__ C_mat,
                            const float* __restrict__ D_vec)
{
    int row = blockIdx.x;
    int tx  = threadIdx.x;      /* 256 */
    __shared__ float hrow[NSTATE];
    if (tx < NSTATE) hrow[tx] = g_hs[row*NSTATE + tx];
    __syncthreads();

    for (int d = tx; d < DINNER; d += 256) {
        const float4* c4 = (const float4*)(C_mat + (size_t)d*NSTATE);
        float acc = 0.f;
        #pragma unroll
        for (int qq = 0; qq < 4; qq++) {
            float4 c = c4[qq];
            acc += c.x*hrow[qq*4+0] + c.y*hrow[qq*4+1]
                 + c.z*hrow[qq*4+2] + c.w*hrow[qq*4+3];
        }
        float xv = g_xs[(size_t)row*DINNER + d];
        float gt = g_xg[(size_t)row*(2*DINNER) + DINNER + d];
        float sg = gt / (1.f + __expf(-gt));
        g_y[(size_t)row*DINNER + d] = (acc + D_vec[d]*xv) * sg;
    }
}

/* ------------------------------------------------------------------ */
extern "C" void kernel_launch(void* const* d_in, const int* in_sizes, int n_in,
                              void* d_out, int out_size)
{
    const float* x        = (const float*)d_in[0];
    const float* ln_gamma = (const float*)d_in[1];
    const float* ln_beta  = (const float*)d_in[2];
    const float* W_in     = (const float*)d_in[3];
    const float* conv_w   = (const float*)d_in[4];
    const float* conv_b   = (const float*)d_in[5];
    const float* A_log    = (const float*)d_in[6];
    const float* B_mat    = (const float*)d_in[7];
    const float* C_mat    = (const float*)d_in[8];
    const float* D_vec    = (const float*)d_in[9];
    const float* Wd       = (const float*)d_in[10];
    const float* bd       = (const float*)d_in[11];
    const float* W_out    = (const float*)d_in[12];
    float* out = (float*)d_out;

    float *p_h, *p_xg, *p_xs, *p_delta, *p_y, *p_wt;
    cudaGetSymbolAddress((void**)&p_h,     g_h);
    cudaGetSymbolAddress((void**)&p_xg,    g_xg);
    cudaGetSymbolAddress((void**)&p_xs,    g_xs);
    cudaGetSymbolAddress((void**)&p_delta, g_delta);
    cudaGetSymbolAddress((void**)&p_y,     g_y);
    cudaGetSymbolAddress((void**)&p_wt,    g_wt);

    cudaFuncSetAttribute(mm_gemm_kernel<0>,
        cudaFuncAttributeMaxDynamicSharedMemorySize, GSMEM_BYTES);
    cudaFuncSetAttribute(mm_gemm_kernel<1>,
        cudaFuncAttributeMaxDynamicSharedMemorySize, GSMEM_BYTES);
    cudaFuncSetAttribute(mm_gemm_kernel<2>,
        cudaFuncAttributeMaxDynamicSharedMemorySize, GSMEM_BYTES);

    /* 1. LayerNorm */
    ln_kernel<<<ROWS, 256>>>(x, ln_gamma, ln_beta);

    /* delta accumulator -> 0 */
    zero_delta_kernel<<<(ROWS+255)/256, 256>>>();

    /* 2. W_in^T, then xg = h @ W_in   (4096 x 4096 x 1024) */
    transpose_tf32_kernel<<<dim3((2*DINNER)/32, DMODEL/32), dim3(32,8)>>>(
        W_in, p_wt, DMODEL, 2*DINNER);
    mm_gemm_kernel<0><<<dim3((2*DINNER)/128, ROWS/128), 256, GSMEM_BYTES>>>(
        p_h, p_wt, p_xg, ROWS, 2*DINNER, DMODEL, nullptr, nullptr, nullptr);

    /* 3. depthwise causal conv + SiLU */
    conv_silu_kernel<<<dim3(DINNER/256, LSEQ/CONV_CH, BSZ), 256>>>(conv_w, conv_b);

    /* 4. Wd^T, then delta row-sums = sum softplus(xs @ Wd + bd) */
    transpose_tf32_kernel<<<dim3(DINNER/32, DINNER/32), dim3(32,8)>>>(
        Wd, p_wt, DINNER, DINNER);
    mm_gemm_kernel<1><<<dim3(DINNER/128, ROWS/128), 256, GSMEM_BYTES>>>(
        p_xs, p_wt, nullptr, ROWS, DINNER, DINNER, bd, p_delta, nullptr);

    /* 5. Bx, dA */
    bxda_kernel<<<ROWS, 128>>>(B_mat, A_log);

    /* 6. scan over L */
    scan_kernel<<<BSZ*NSTATE, 1024>>>();

    /* 7. y = (hs @ C^T + D*xs) * silu(gate) */
    ymix_kernel<<<ROWS, 256>>>(C_mat, D_vec);

    /* 8. W_out^T, then out = y @ W_out + x   (4096 x 1024 x 2048) */
    transpose_tf32_kernel<<<dim3(DMODEL/32, DINNER/32), dim3(32,8)>>>(
        W_out, p_wt, DINNER, DMODEL);
    mm_gemm_kernel<2><<<dim3(DMODEL/128, ROWS/128), 256, GSMEM_BYTES>>>(
        p_y, p_wt, out, ROWS, DMODEL, DINNER, nullptr, nullptr, x);
}

// round 4
// speedup vs baseline: 3.3803x; 1.6663x over previous
#include <cuda_runtime.h>
#include <cuda_bf16.h>
#include <math.h>
#include <stdint.h>

#define BSZ 2
#define LSEQ 2048
#define DMODEL 1024
#define DINNER 2048
#define NSTATE 16
#define ROWS (BSZ*LSEQ)   /* 4096 */

/* ------------------------------------------------------------------ */
/* Scratch (static __device__ globals; allocation-free per harness)   */
/* ------------------------------------------------------------------ */
__device__ float g_h   [(size_t)ROWS*DMODEL];     /* post-LN            */
__device__ float g_xg  [(size_t)ROWS*2*DINNER];   /* h @ W_in           */
__device__ float g_xs  [(size_t)ROWS*DINNER];     /* conv+silu          */
__device__ float g_delta[ROWS];                   /* row sums -> delta  */
__device__ float g_dA  [(size_t)ROWS*NSTATE];
__device__ float g_Bx  [(size_t)ROWS*NSTATE];
__device__ float g_hs  [(size_t)ROWS*NSTATE];
__device__ float g_y   [(size_t)ROWS*DINNER];     /* pre-W_out          */
__device__ __nv_bfloat16 g_wt[(size_t)4096*2048]; /* transposed bf16 weight */

__device__ __forceinline__ uint32_t smem_u32(const void* p) {
    uint32_t a;
    asm("{ .reg .u64 t; cvta.to.shared.u64 t, %1; cvt.u32.u64 %0, t; }" : "=r"(a) : "l"(p));
    return a;
}

/* ------------------------------------------------------------------ */
/* LayerNorm: one block per row of 1024                               */
/* ------------------------------------------------------------------ */
__global__ void ln_kernel(const float* __restrict__ x,
                          const float* __restrict__ gamma,
                          const float* __restrict__ beta)
{
    int row = blockIdx.x;
    int tx  = threadIdx.x;                       /* 256 threads */
    const float4* xr = (const float4*)(x + (size_t)row*DMODEL);
    float4 v = xr[tx];
    float s  = v.x + v.y + v.z + v.w;
    float ss = v.x*v.x + v.y*v.y + v.z*v.z + v.w*v.w;
    #pragma unroll
    for (int o = 16; o; o >>= 1) {
        s  += __shfl_down_sync(0xffffffffu, s,  o);
        ss += __shfl_down_sync(0xffffffffu, ss, o);
    }
    __shared__ float sh[8], sh2[8];
    int w = tx >> 5, l = tx & 31;
    if (l == 0) { sh[w] = s; sh2[w] = ss; }
    __syncthreads();
    if (tx == 0) {
        float S = 0.f, SS = 0.f;
        #pragma unroll
        for (int i = 0; i < 8; i++) { S += sh[i]; SS += sh2[i]; }
        sh[0]  = S  * (1.0f/DMODEL);
        sh2[0] = SS * (1.0f/DMODEL);
    }
    __syncthreads();
    float mean = sh[0];
    float var  = sh2[0] - mean*mean;
    float r    = rsqrtf(var + 1e-5f);
    float4 gg = ((const float4*)gamma)[tx];
    float4 bb = ((const float4*)beta )[tx];
    float4 o;
    o.x = (v.x - mean)*r*gg.x + bb.x;
    o.y = (v.y - mean)*r*gg.y + bb.y;
    o.z = (v.z - mean)*r*gg.z + bb.z;
    o.w = (v.w - mean)*r*gg.w + bb.w;
    ((float4*)(g_h + (size_t)row*DMODEL))[tx] = o;
}

__global__ void zero_delta_kernel()
{
    int i = blockIdx.x*256 + threadIdx.x;
    if (i < ROWS) g_delta[i] = 0.f;
}

/* ------------------------------------------------------------------ */
/* Transpose weight [K,N] fp32 -> [N,K] bf16.                         */
/* ------------------------------------------------------------------ */
__global__ void transpose_bf16_kernel(const float* __restrict__ W,
                                      __nv_bfloat16* __restrict__ Wt, int K, int N)
{
    __shared__ float tile[32][33];
    int n0 = blockIdx.x*32, k0 = blockIdx.y*32;
    int tx = threadIdx.x, ty = threadIdx.y;
    #pragma unroll
    for (int i = 0; i < 32; i += 8)
        tile[ty+i][tx] = W[(size_t)(k0+ty+i)*N + n0+tx];
    __syncthreads();
    #pragma unroll
    for (int i = 0; i < 32; i += 8)
        Wt[(size_t)(n0+ty+i)*K + k0+tx] = __float2bfloat16_rn(tile[tx][ty+i]);
}

/* ------------------------------------------------------------------ */
/* bf16 mma.sync GEMM with ldmatrix:                                  */
/*   C(MxN) = A_fp32(MxK) @ Wt_bf16(NxK)^T                            */
/* CTA tile 128x128, BK=32, 8 warps, warp tile 64x32, m16n8k16.       */
/* smem rows padded to 40 bf16 (80B) -> conflict-free ldmatrix.       */
/* MODE 0: plain store  MODE 1: rowsum += softplus(acc+bias)          */
/* MODE 2: C = acc + resid                                            */
/* ------------------------------------------------------------------ */
#define SROW 80                      /* bytes per smem row  */
#define TILEB (128*SROW)             /* 10240 B per buffer  */

#define LDSM4(r0,r1,r2,r3, addr) \
    asm volatile("ldmatrix.sync.aligned.m8n8.x4.shared.b16 {%0,%1,%2,%3}, [%4];" \
        : "=r"(r0),"=r"(r1),"=r"(r2),"=r"(r3) : "r"(addr))

#define MMA_BF16(c, a, b0v, b1v) \
    asm volatile("mma.sync.aligned.m16n8k16.row.col.f32.bf16.bf16.f32 " \
        "{%0,%1,%2,%3},{%4,%5,%6,%7},{%8,%9},{%0,%1,%2,%3};" \
        : "+f"((c)[0]),"+f"((c)[1]),"+f"((c)[2]),"+f"((c)[3]) \
        : "r"((a)[0]),"r"((a)[1]),"r"((a)[2]),"r"((a)[3]), "r"(b0v),"r"(b1v))

template<int MODE>
__global__ __launch_bounds__(256)
void mm_gemm_kernel(const float* __restrict__ A, const __nv_bfloat16* __restrict__ Bt,
                    float* __restrict__ C, int M, int N, int Kd,
                    const float* __restrict__ bias,
                    float* __restrict__ rowsum,
                    const float* __restrict__ resid)
{
    __shared__ __align__(16) unsigned char gsm[4*TILEB];  /* A0,A1,B0,B1 */
    uint32_t sbase = smem_u32(gsm);

    int tid  = threadIdx.x;
    int wid  = tid >> 5;
    int lane = tid & 31;
    int g    = lane >> 2;      /* fragment row group 0..7 */
    int q    = lane & 3;       /* quad lane 0..3          */
    int mwb  = (wid & 1) * 64; /* warp m-base within CTA  */
    int nwb  = (wid >> 1) * 32;/* warp n-base within CTA  */
    int row0 = blockIdx.y * 128;
    int col0 = blockIdx.x * 128;

    const float*         Ab = A  + (size_t)row0*Kd;
    const __nv_bfloat16* Bb = Bt + (size_t)col0*Kd;

    /* per-lane ldmatrix intra-tile offsets */
    int r8 = lane & 7;
    uint32_t laneA = (uint32_t)((r8 + ((lane>>3)&1)*8)*SROW + ((lane>>4)&1)*16);
    uint32_t laneB = (uint32_t)((r8 + ((lane>>4)&1)*8)*SROW + ((lane>>3)&1)*16);

    /* staging indices */
    int rA = tid >> 3, cA = tid & 7;    /* A: 4 iters rows +32, float4 cols */
    int rB = tid >> 2, cB = tid & 3;    /* B: 2 iters rows +64, uint4 cols  */

    float acc[4][4][4];
    #pragma unroll
    for (int mt = 0; mt < 4; mt++)
        #pragma unroll
        for (int nt = 0; nt < 4; nt++)
            #pragma unroll
            for (int j = 0; j < 4; j++) acc[mt][nt][j] = 0.f;

    const int nch = Kd >> 5;

    /* --- stage chunk 0 --- */
    #pragma unroll
    for (int i = 0; i < 4; i++) {
        int r = rA + 32*i;
        float4 v = *(const float4*)(Ab + (size_t)r*Kd + cA*4);
        __nv_bfloat162 lo = __floats2bfloat162_rn(v.x, v.y);
        __nv_bfloat162 hi = __floats2bfloat162_rn(v.z, v.w);
        *(uint2*)(gsm + r*SROW + cA*8) =
            make_uint2(*(uint32_t*)&lo, *(uint32_t*)&hi);
    }
    #pragma unroll
    for (int i = 0; i < 2; i++) {
        int r = rB + 64*i;
        uint4 w = *(const uint4*)(Bb + (size_t)r*Kd + cB*8);
        *(uint4*)(gsm + 2*TILEB + r*SROW + cB*16) = w;
    }
    __syncthreads();

    float4 pA[4]; uint4 pB[2];
    for (int c = 0; c < nch; c++) {
        int cur = c & 1, nxt = cur ^ 1;
        bool more = (c + 1 < nch);
        if (more) {
            const float*         An = Ab + (c+1)*32;
            const __nv_bfloat16* Bn = Bb + (c+1)*32;
            #pragma unroll
            for (int i = 0; i < 4; i++)
                pA[i] = *(const float4*)(An + (size_t)(rA + 32*i)*Kd + cA*4);
            #pragma unroll
            for (int i = 0; i < 2; i++)
                pB[i] = *(const uint4*)(Bn + (size_t)(rB + 64*i)*Kd + cB*8);
        }

        /* --- compute on buffer cur --- */
        uint32_t aBase = sbase + cur*TILEB            + laneA;
        uint32_t bBase = sbase + 2*TILEB + cur*TILEB  + laneB;
        #pragma unroll
        for (int ks = 0; ks < 2; ks++) {
            uint32_t af[4][4], bf4[2][4];
            #pragma unroll
            for (int mt = 0; mt < 4; mt++)
                LDSM4(af[mt][0], af[mt][1], af[mt][2], af[mt][3],
                      aBase + (uint32_t)((mwb + mt*16)*SROW + ks*32));
            #pragma unroll
            for (int np = 0; np < 2; np++)
                LDSM4(bf4[np][0], bf4[np][1], bf4[np][2], bf4[np][3],
                      bBase + (uint32_t)((nwb + np*16)*SROW + ks*32));
            #pragma unroll
            for (int mt = 0; mt < 4; mt++)
                #pragma unroll
                for (int nt = 0; nt < 4; nt++)
                    MMA_BF16(acc[mt][nt], af[mt],
                             bf4[nt>>1][(nt&1)*2], bf4[nt>>1][(nt&1)*2+1]);
        }

        if (more) {
            #pragma unroll
            for (int i = 0; i < 4; i++) {
                __nv_bfloat162 lo = __floats2bfloat162_rn(pA[i].x, pA[i].y);
                __nv_bfloat162 hi = __floats2bfloat162_rn(pA[i].z, pA[i].w);
                *(uint2*)(gsm + nxt*TILEB + (rA + 32*i)*SROW + cA*8) =
                    make_uint2(*(uint32_t*)&lo, *(uint32_t*)&hi);
            }
            #pragma unroll
            for (int i = 0; i < 2; i++)
                *(uint4*)(gsm + 2*TILEB + nxt*TILEB + (rB + 64*i)*SROW + cB*16) = pB[i];
        }
        __syncthreads();
    }

    /* --------------------------- epilogue -------------------------- */
    if (MODE == 1) {
        float part[4][2];
        #pragma unroll
        for (int mt = 0; mt < 4; mt++) {
            float s0 = 0.f, s1 = 0.f;
            #pragma unroll
            for (int nt = 0; nt < 4; nt++) {
                int colb = col0 + nwb + nt*8 + 2*q;
                float b0 = bias[colb], b1 = bias[colb+1];
                float z;
                z = acc[mt][nt][0] + b0; s0 += (z > 20.f) ? z : log1pf(__expf(z));
                z = acc[mt][nt][1] + b1; s0 += (z > 20.f) ? z : log1pf(__expf(z));
                z = acc[mt][nt][2] + b0; s1 += (z > 20.f) ? z : log1pf(__expf(z));
                z = acc[mt][nt][3] + b1; s1 += (z > 20.f) ? z : log1pf(__expf(z));
            }
            part[mt][0] = s0; part[mt][1] = s1;
        }
        float* red = (float*)gsm;
        if (tid < 128) red[tid] = 0.f;
        __syncthreads();
        #pragma unroll
        for (int mt = 0; mt < 4; mt++) {
            atomicAdd(&red[mwb + mt*16 + g    ], part[mt][0]);
            atomicAdd(&red[mwb + mt*16 + g + 8], part[mt][1]);
        }
        __syncthreads();
        if (tid < 128)
            atomicAdd(&rowsum[row0 + tid], red[tid]);
    } else {
        #pragma unroll
        for (int mt = 0; mt < 4; mt++) {
            int r0 = row0 + mwb + mt*16 + g;
            #pragma unroll
            for (int nt = 0; nt < 4; nt++) {
                int col = col0 + nwb + nt*8 + 2*q;
                float2 o0 = make_float2(acc[mt][nt][0], acc[mt][nt][1]);
                float2 o1 = make_float2(acc[mt][nt][2], acc[mt][nt][3]);
                if (MODE == 2) {
                    float2 rr0 = *(const float2*)(resid + (size_t)r0*N + col);
                    float2 rr1 = *(const float2*)(resid + (size_t)(r0+8)*N + col);
                    o0.x += rr0.x; o0.y += rr0.y;
                    o1.x += rr1.x; o1.y += rr1.y;
                }
                *(float2*)(C + (size_t)r0*N + col)     = o0;
                *(float2*)(C + (size_t)(r0+8)*N + col) = o1;
            }
        }
    }
}

/* ------------------------------------------------------------------ */
/* Depthwise causal conv (K=4) + bias + SiLU, 4-way unrolled (MLP=4). */
/* ------------------------------------------------------------------ */
#define CONV_CH 64
__global__ void conv_silu_kernel(const float* __restrict__ conv_w,
                                 const float* __restrict__ conv_b)
{
    int d  = blockIdx.x*256 + threadIdx.x;    /* 0..2047 */
    int b  = blockIdx.z;
    int l0 = blockIdx.y * CONV_CH;

    float4 w4 = *(const float4*)(conv_w + d*4);  /* w[0..3] */
    float cb  = conv_b[d];

    const float* xgp = g_xg;
    float p1 = (l0 >= 1) ? xgp[((size_t)(b*LSEQ + l0-1))*(2*DINNER) + d] : 0.f;
    float p2 = (l0 >= 2) ? xgp[((size_t)(b*LSEQ + l0-2))*(2*DINNER) + d] : 0.f;
    float p3 = (l0 >= 3) ? xgp[((size_t)(b*LSEQ + l0-3))*(2*DINNER) + d] : 0.f;

    for (int i = 0; i < CONV_CH; i += 4) {
        int l = l0 + i;
        size_t base = ((size_t)(b*LSEQ + l))*(2*DINNER) + d;
        float c0 = xgp[base];
        float c1 = xgp[base + 1*(2*DINNER)];
        float c2 = xgp[base + 2*(2*DINNER)];
        float c3 = xgp[base + 3*(2*DINNER)];
        float v0 = w4.x*p3 + w4.y*p2 + w4.z*p1 + w4.w*c0 + cb;
        float v1 = w4.x*p2 + w4.y*p1 + w4.z*c0 + w4.w*c1 + cb;
        float v2 = w4.x*p1 + w4.y*c0 + w4.z*c1 + w4.w*c2 + cb;
        float v3 = w4.x*c0 + w4.y*c1 + w4.z*c2 + w4.w*c3 + cb;
        size_t ob = ((size_t)(b*LSEQ + l))*DINNER + d;
        g_xs[ob              ] = v0 / (1.f + __expf(-v0));
        g_xs[ob + 1*DINNER   ] = v1 / (1.f + __expf(-v1));
        g_xs[ob + 2*DINNER   ] = v2 / (1.f + __expf(-v2));
        g_xs[ob + 3*DINNER   ] = v3 / (1.f + __expf(-v3));
        p3 = c1; p2 = c2; p1 = c3;
    }
}

/* ------------------------------------------------------------------ */
/* Bx + dA: 8 rows per block (one warp per row) -> B_mat L1 reuse.    */
/* ------------------------------------------------------------------ */
__global__ void bxda_kernel(const float* __restrict__ B_mat,
                            const float* __restrict__ A_log)
{
    int row  = blockIdx.x*8 + (threadIdx.x >> 5);
    int lane = threadIdx.x & 31;

    float sums[NSTATE];
    #pragma unroll
    for (int n = 0; n < NSTATE; n++) sums[n] = 0.f;

    const float* xr = g_xs + (size_t)row*DINNER;
    for (int d = lane; d < DINNER; d += 32) {
        float xv = xr[d];
        #pragma unroll
        for (int n = 0; n < NSTATE; n++)
            sums[n] += xv * B_mat[n*DINNER + d];
    }
    #pragma unroll
    for (int n = 0; n < NSTATE; n++)
        #pragma unroll
        for (int o = 16; o; o >>= 1)
            sums[n] += __shfl_xor_sync(0xffffffffu, sums[n], o);

    if (lane < NSTATE) {
        float delta = g_delta[row] * (1.0f/DINNER);
        float An    = -__expf(A_log[lane]);
        g_Bx[row*NSTATE + lane] = sums[lane] * delta;
        g_dA[row*NSTATE + lane] = __expf(delta * An);
    }
}

/* ------------------------------------------------------------------ */
/* Parallel scan (Hillis-Steele over affine maps)                     */
/* ------------------------------------------------------------------ */
__global__ __launch_bounds__(1024)
void scan_kernel()
{
    __shared__ float Aa[2][LSEQ];
    __shared__ float Bb[2][LSEQ];
    int bn = blockIdx.x;
    int b  = bn >> 4;
    int n  = bn & 15;
    int tid = threadIdx.x;

    for (int l = tid; l < LSEQ; l += 1024) {
        size_t idx = ((size_t)(b*LSEQ + l))*NSTATE + n;
        Aa[0][l] = g_dA[idx];
        Bb[0][l] = g_Bx[idx];
    }
    __syncthreads();
    int src = 0;
    for (int off = 1; off < LSEQ; off <<= 1) {
        int dst = src ^ 1;
        for (int l = tid; l < LSEQ; l += 1024) {
            float a = Aa[src][l], bv = Bb[src][l];
            if (l >= off) {
                float ap = Aa[src][l-off], bp = Bb[src][l-off];
                Aa[dst][l] = a * ap;
                Bb[dst][l] = a * bp + bv;
            } else {
                Aa[dst][l] = a;
                Bb[dst][l] = bv;
            }
        }
        __syncthreads();
        src ^= 1;
    }
    for (int l = tid; l < LSEQ; l += 1024) {
        size_t idx = ((size_t)(b*LSEQ + l))*NSTATE + n;
        g_hs[idx] = Bb[src][l];
    }
}

/* ------------------------------------------------------------------ */
/* y = (hs @ C^T + D*xs) * silu(gate)                                 */
/* ------------------------------------------------------------------ */
__global__ void ymix_kernel(const float* __restrict__ C_mat,
                            const float* __restrict__ D_vec)
{
    int row = blockIdx.x;
    int tx  = threadIdx.x;      /* 256 */
    __shared__ float hrow[NSTATE];
    if (tx < NSTATE) hrow[tx] = g_hs[row*NSTATE + tx];
    __syncthreads();

    for (int d = tx; d < DINNER; d += 256) {
        const float4* c4 = (const float4*)(C_mat + (size_t)d*NSTATE);
        float acc = 0.f;
        #pragma unroll
        for (int qq = 0; qq < 4; qq++) {
            float4 c = c4[qq];
            acc += c.x*hrow[qq*4+0] + c.y*hrow[qq*4+1]
                 + c.z*hrow[qq*4+2] + c.w*hrow[qq*4+3];
        }
        float xv = g_xs[(size_t)row*DINNER + d];
        float gt = g_xg[(size_t)row*(2*DINNER) + DINNER + d];
        float sg = gt / (1.f + __expf(-gt));
        g_y[(size_t)row*DINNER + d] = (acc + D_vec[d]*xv) * sg;
    }
}

/* ------------------------------------------------------------------ */
extern "C" void kernel_launch(void* const* d_in, const int* in_sizes, int n_in,
                              void* d_out, int out_size)
{
    const float* x        = (const float*)d_in[0];
    const float* ln_gamma = (const float*)d_in[1];
    const float* ln_beta  = (const float*)d_in[2];
    const float* W_in     = (const float*)d_in[3];
    const float* conv_w   = (const float*)d_in[4];
    const float* conv_b   = (const float*)d_in[5];
    const float* A_log    = (const float*)d_in[6];
    const float* B_mat    = (const float*)d_in[7];
    const float* C_mat    = (const float*)d_in[8];
    const float* D_vec    = (const float*)d_in[9];
    const float* Wd       = (const float*)d_in[10];
    const float* bd       = (const float*)d_in[11];
    const float* W_out    = (const float*)d_in[12];
    float* out = (float*)d_out;

    float *p_h, *p_xg, *p_xs, *p_delta, *p_y;
    __nv_bfloat16* p_wt;
    cudaGetSymbolAddress((void**)&p_h,     g_h);
    cudaGetSymbolAddress((void**)&p_xg,    g_xg);
    cudaGetSymbolAddress((void**)&p_xs,    g_xs);
    cudaGetSymbolAddress((void**)&p_delta, g_delta);
    cudaGetSymbolAddress((void**)&p_y,     g_y);
    cudaGetSymbolAddress((void**)&p_wt,    g_wt);

    /* 1. LayerNorm */
    ln_kernel<<<ROWS, 256>>>(x, ln_gamma, ln_beta);

    /* delta accumulator -> 0 */
    zero_delta_kernel<<<(ROWS+255)/256, 256>>>();

    /* 2. W_in^T (bf16), then xg = h @ W_in   (4096 x 4096 x 1024) */
    transpose_bf16_kernel<<<dim3((2*DINNER)/32, DMODEL/32), dim3(32,8)>>>(
        W_in, p_wt, DMODEL, 2*DINNER);
    mm_gemm_kernel<0><<<dim3((2*DINNER)/128, ROWS/128), 256>>>(
        p_h, p_wt, p_xg, ROWS, 2*DINNER, DMODEL, nullptr, nullptr, nullptr);

    /* 3. depthwise causal conv + SiLU */
    conv_silu_kernel<<<dim3(DINNER/256, LSEQ/CONV_CH, BSZ), 256>>>(conv_w, conv_b);

    /* 4. Wd^T (bf16), then delta row-sums = sum softplus(xs @ Wd + bd) */
    transpose_bf16_kernel<<<dim3(DINNER/32, DINNER/32), dim3(32,8)>>>(
        Wd, p_wt, DINNER, DINNER);
    mm_gemm_kernel<1><<<dim3(DINNER/128, ROWS/128), 256>>>(
        p_xs, p_wt, nullptr, ROWS, DINNER, DINNER, bd, p_delta, nullptr);

    /* 5. Bx, dA */
    bxda_kernel<<<ROWS/8, 256>>>(B_mat, A_log);

    /* 6. scan over L */
    scan_kernel<<<BSZ*NSTATE, 1024>>>();

    /* 7. y = (hs @ C^T + D*xs) * silu(gate) */
    ymix_kernel<<<ROWS, 256>>>(C_mat, D_vec);

    /* 8. W_out^T (bf16), then out = y @ W_out + x   (4096 x 1024 x 2048) */
    transpose_bf16_kernel<<<dim3(DMODEL/32, DINNER/32), dim3(32,8)>>>(
        W_out, p_wt, DINNER, DMODEL);
    mm_gemm_kernel<2><<<dim3(DMODEL/128, ROWS/128), 256>>>(
        p_y, p_wt, out, ROWS, DMODEL, DINNER, nullptr, nullptr, x);
}

// round 5
// speedup vs baseline: 4.6154x; 1.3654x over previous
#include <cuda_runtime.h>
#include <cuda_bf16.h>
#include <math.h>
#include <stdint.h>

#define BSZ 2
#define LSEQ 2048
#define DMODEL 1024
#define DINNER 2048
#define NSTATE 16
#define ROWS (BSZ*LSEQ)   /* 4096 */

/* ------------------------------------------------------------------ */
/* Scratch                                                            */
/* ------------------------------------------------------------------ */
__device__ __nv_bfloat16 g_hb [(size_t)ROWS*DMODEL];   /* post-LN (bf16)   */
__device__ float g_xg  [(size_t)ROWS*2*DINNER];        /* h @ W_in         */
__device__ float g_xs  [(size_t)ROWS*DINNER];          /* conv+silu fp32   */
__device__ __nv_bfloat16 g_xs_bf[(size_t)ROWS*DINNER]; /* conv+silu bf16   */
__device__ float g_delta[ROWS];
__device__ float g_dA  [(size_t)ROWS*NSTATE];
__device__ float g_Bx  [(size_t)ROWS*NSTATE];
__device__ float g_hs  [(size_t)ROWS*NSTATE];
__device__ __nv_bfloat16 g_yb [(size_t)ROWS*DINNER];   /* pre-W_out (bf16) */
__device__ __nv_bfloat16 g_wt [(size_t)4096*2048];     /* transposed bf16 W */

__device__ __forceinline__ uint32_t smem_u32(const void* p) {
    uint32_t a;
    asm("{ .reg .u64 t; cvta.to.shared.u64 t, %1; cvt.u32.u64 %0, t; }" : "=r"(a) : "l"(p));
    return a;
}

/* ------------------------------------------------------------------ */
/* LayerNorm: one block per row of 1024, writes bf16                  */
/* ------------------------------------------------------------------ */
__global__ void ln_kernel(const float* __restrict__ x,
                          const float* __restrict__ gamma,
                          const float* __restrict__ beta)
{
    int row = blockIdx.x;
    int tx  = threadIdx.x;                       /* 256 threads */
    const float4* xr = (const float4*)(x + (size_t)row*DMODEL);
    float4 v = xr[tx];
    float s  = v.x + v.y + v.z + v.w;
    float ss = v.x*v.x + v.y*v.y + v.z*v.z + v.w*v.w;
    #pragma unroll
    for (int o = 16; o; o >>= 1) {
        s  += __shfl_down_sync(0xffffffffu, s,  o);
        ss += __shfl_down_sync(0xffffffffu, ss, o);
    }
    __shared__ float sh[8], sh2[8];
    int w = tx >> 5, l = tx & 31;
    if (l == 0) { sh[w] = s; sh2[w] = ss; }
    __syncthreads();
    if (tx == 0) {
        float S = 0.f, SS = 0.f;
        #pragma unroll
        for (int i = 0; i < 8; i++) { S += sh[i]; SS += sh2[i]; }
        sh[0]  = S  * (1.0f/DMODEL);
        sh2[0] = SS * (1.0f/DMODEL);
    }
    __syncthreads();
    float mean = sh[0];
    float var  = sh2[0] - mean*mean;
    float r    = rsqrtf(var + 1e-5f);
    float4 gg = ((const float4*)gamma)[tx];
    float4 bb = ((const float4*)beta )[tx];
    __nv_bfloat162 lo = __floats2bfloat162_rn((v.x - mean)*r*gg.x + bb.x,
                                              (v.y - mean)*r*gg.y + bb.y);
    __nv_bfloat162 hi = __floats2bfloat162_rn((v.z - mean)*r*gg.z + bb.z,
                                              (v.w - mean)*r*gg.w + bb.w);
    *(uint2*)(g_hb + (size_t)row*DMODEL + tx*4) =
        make_uint2(*(uint32_t*)&lo, *(uint32_t*)&hi);
}

__global__ void zero_delta_kernel()
{
    int i = blockIdx.x*256 + threadIdx.x;
    if (i < ROWS) g_delta[i] = 0.f;
}

/* ------------------------------------------------------------------ */
/* Transpose weight [K,N] fp32 -> [N,K] bf16.                         */
/* ------------------------------------------------------------------ */
__global__ void transpose_bf16_kernel(const float* __restrict__ W,
                                      __nv_bfloat16* __restrict__ Wt, int K, int N)
{
    __shared__ float tile[32][33];
    int n0 = blockIdx.x*32, k0 = blockIdx.y*32;
    int tx = threadIdx.x, ty = threadIdx.y;
    #pragma unroll
    for (int i = 0; i < 32; i += 8)
        tile[ty+i][tx] = W[(size_t)(k0+ty+i)*N + n0+tx];
    __syncthreads();
    #pragma unroll
    for (int i = 0; i < 32; i += 8)
        Wt[(size_t)(n0+ty+i)*K + k0+tx] = __float2bfloat16_rn(tile[tx][ty+i]);
}

/* ------------------------------------------------------------------ */
/* bf16 mma.sync GEMM, cp.async 3-stage pipeline:                     */
/*   C(MxN) = A_bf16(MxK) @ Wt_bf16(NxK)^T                            */
/* CTA 128x128, BK=32, 8 warps (warp tile 64x32), m16n8k16+ldmatrix.  */
/* ------------------------------------------------------------------ */
#define SROW 80                      /* bytes per smem row  */
#define TILEB (128*SROW)             /* 10240 B per operand */
#define STAGEB (2*TILEB)             /* A+B per stage       */
#define NSTG 3

#define CPASYNC16(dst, src) \
    asm volatile("cp.async.cg.shared.global [%0], [%1], 16;" :: "r"(dst), "l"(src))
#define CP_COMMIT() asm volatile("cp.async.commit_group;" ::: "memory")
#define CP_WAIT1()  asm volatile("cp.async.wait_group 1;" ::: "memory")

#define LDSM4(r0,r1,r2,r3, addr) \
    asm volatile("ldmatrix.sync.aligned.m8n8.x4.shared.b16 {%0,%1,%2,%3}, [%4];" \
        : "=r"(r0),"=r"(r1),"=r"(r2),"=r"(r3) : "r"(addr))

#define MMA_BF16(c, a, b0v, b1v) \
    asm volatile("mma.sync.aligned.m16n8k16.row.col.f32.bf16.bf16.f32 " \
        "{%0,%1,%2,%3},{%4,%5,%6,%7},{%8,%9},{%0,%1,%2,%3};" \
        : "+f"((c)[0]),"+f"((c)[1]),"+f"((c)[2]),"+f"((c)[3]) \
        : "r"((a)[0]),"r"((a)[1]),"r"((a)[2]),"r"((a)[3]), "r"(b0v),"r"(b1v))

__device__ __forceinline__ void stage_issue(uint32_t sbase, int stage,
                                            const __nv_bfloat16* Ab,
                                            const __nv_bfloat16* Bb,
                                            int Kd, int c, int tid)
{
    uint32_t sA = sbase + stage*STAGEB;
    uint32_t sB = sA + TILEB;
    int seg = tid & 3;
    int row = tid >> 2;                 /* 0..63 */
    #pragma unroll
    for (int i = 0; i < 2; i++) {
        int r = row + 64*i;
        CPASYNC16(sA + (uint32_t)(r*SROW + seg*16),
                  Ab + (size_t)r*Kd + c*32 + seg*8);
        CPASYNC16(sB + (uint32_t)(r*SROW + seg*16),
                  Bb + (size_t)r*Kd + c*32 + seg*8);
    }
}

template<int MODE>
__global__ __launch_bounds__(256, 2)
void mm_gemm_kernel(const __nv_bfloat16* __restrict__ A,
                    const __nv_bfloat16* __restrict__ Bt,
                    float* __restrict__ C, int M, int N, int Kd,
                    const float* __restrict__ bias,
                    float* __restrict__ rowsum,
                    const float* __restrict__ resid)
{
    __shared__ __align__(16) unsigned char gsm[NSTG*STAGEB];
    uint32_t sbase = smem_u32(gsm);

    int tid  = threadIdx.x;
    int wid  = tid >> 5;
    int lane = tid & 31;
    int g    = lane >> 2;
    int q    = lane & 3;
    int mwb  = (wid & 1) * 64;
    int nwb  = (wid >> 1) * 32;
    int row0 = blockIdx.y * 128;
    int col0 = blockIdx.x * 128;

    const __nv_bfloat16* Ab = A  + (size_t)row0*Kd;
    const __nv_bfloat16* Bb = Bt + (size_t)col0*Kd;

    int r8 = lane & 7;
    uint32_t laneA = (uint32_t)((r8 + ((lane>>3)&1)*8)*SROW + ((lane>>4)&1)*16);
    uint32_t laneB = (uint32_t)((r8 + ((lane>>4)&1)*8)*SROW + ((lane>>3)&1)*16);

    float acc[4][4][4];
    #pragma unroll
    for (int mt = 0; mt < 4; mt++)
        #pragma unroll
        for (int nt = 0; nt < 4; nt++)
            #pragma unroll
            for (int j = 0; j < 4; j++) acc[mt][nt][j] = 0.f;

    const int nch = Kd >> 5;

    stage_issue(sbase, 0, Ab, Bb, Kd, 0, tid); CP_COMMIT();
    stage_issue(sbase, 1, Ab, Bb, Kd, 1, tid); CP_COMMIT();

    for (int c = 0; c < nch; c++) {
        CP_WAIT1();
        __syncthreads();
        if (c + 2 < nch)
            stage_issue(sbase, (c+2)%NSTG, Ab, Bb, Kd, c+2, tid);
        CP_COMMIT();

        uint32_t aBase = sbase + (c%NSTG)*STAGEB          + laneA;
        uint32_t bBase = sbase + (c%NSTG)*STAGEB + TILEB  + laneB;
        #pragma unroll
        for (int ks = 0; ks < 2; ks++) {
            uint32_t af[4][4], bf4[2][4];
            #pragma unroll
            for (int mt = 0; mt < 4; mt++)
                LDSM4(af[mt][0], af[mt][1], af[mt][2], af[mt][3],
                      aBase + (uint32_t)((mwb + mt*16)*SROW + ks*32));
            #pragma unroll
            for (int np = 0; np < 2; np++)
                LDSM4(bf4[np][0], bf4[np][1], bf4[np][2], bf4[np][3],
                      bBase + (uint32_t)((nwb + np*16)*SROW + ks*32));
            #pragma unroll
            for (int mt = 0; mt < 4; mt++)
                #pragma unroll
                for (int nt = 0; nt < 4; nt++)
                    MMA_BF16(acc[mt][nt], af[mt],
                             bf4[nt>>1][(nt&1)*2], bf4[nt>>1][(nt&1)*2+1]);
        }
    }
    __syncthreads();

    /* --------------------------- epilogue -------------------------- */
    if (MODE == 1) {
        float part[4][2];
        #pragma unroll
        for (int mt = 0; mt < 4; mt++) {
            float s0 = 0.f, s1 = 0.f;
            #pragma unroll
            for (int nt = 0; nt < 4; nt++) {
                int colb = col0 + nwb + nt*8 + 2*q;
                float b0 = bias[colb], b1 = bias[colb+1];
                float z;
                z = acc[mt][nt][0] + b0; s0 += (z > 20.f) ? z : log1pf(__expf(z));
                z = acc[mt][nt][1] + b1; s0 += (z > 20.f) ? z : log1pf(__expf(z));
                z = acc[mt][nt][2] + b0; s1 += (z > 20.f) ? z : log1pf(__expf(z));
                z = acc[mt][nt][3] + b1; s1 += (z > 20.f) ? z : log1pf(__expf(z));
            }
            part[mt][0] = s0; part[mt][1] = s1;
        }
        float* red = (float*)gsm;
        if (tid < 128) red[tid] = 0.f;
        __syncthreads();
        #pragma unroll
        for (int mt = 0; mt < 4; mt++) {
            atomicAdd(&red[mwb + mt*16 + g    ], part[mt][0]);
            atomicAdd(&red[mwb + mt*16 + g + 8], part[mt][1]);
        }
        __syncthreads();
        if (tid < 128)
            atomicAdd(&rowsum[row0 + tid], red[tid]);
    } else {
        #pragma unroll
        for (int mt = 0; mt < 4; mt++) {
            int r0 = row0 + mwb + mt*16 + g;
            #pragma unroll
            for (int nt = 0; nt < 4; nt++) {
                int col = col0 + nwb + nt*8 + 2*q;
                float2 o0 = make_float2(acc[mt][nt][0], acc[mt][nt][1]);
                float2 o1 = make_float2(acc[mt][nt][2], acc[mt][nt][3]);
                if (MODE == 2) {
                    float2 rr0 = *(const float2*)(resid + (size_t)r0*N + col);
                    float2 rr1 = *(const float2*)(resid + (size_t)(r0+8)*N + col);
                    o0.x += rr0.x; o0.y += rr0.y;
                    o1.x += rr1.x; o1.y += rr1.y;
                }
                *(float2*)(C + (size_t)r0*N + col)     = o0;
                *(float2*)(C + (size_t)(r0+8)*N + col) = o1;
            }
        }
    }
}

/* ------------------------------------------------------------------ */
/* Depthwise causal conv (K=4) + bias + SiLU; writes fp32 + bf16.     */
/* ------------------------------------------------------------------ */
#define CONV_CH 64
__global__ void conv_silu_kernel(const float* __restrict__ conv_w,
                                 const float* __restrict__ conv_b)
{
    int d  = blockIdx.x*256 + threadIdx.x;    /* 0..2047 */
    int b  = blockIdx.z;
    int l0 = blockIdx.y * CONV_CH;

    float4 w4 = *(const float4*)(conv_w + d*4);
    float cb  = conv_b[d];

    const float* xgp = g_xg;
    float p1 = (l0 >= 1) ? xgp[((size_t)(b*LSEQ + l0-1))*(2*DINNER) + d] : 0.f;
    float p2 = (l0 >= 2) ? xgp[((size_t)(b*LSEQ + l0-2))*(2*DINNER) + d] : 0.f;
    float p3 = (l0 >= 3) ? xgp[((size_t)(b*LSEQ + l0-3))*(2*DINNER) + d] : 0.f;

    for (int i = 0; i < CONV_CH; i += 4) {
        int l = l0 + i;
        size_t base = ((size_t)(b*LSEQ + l))*(2*DINNER) + d;
        float c0 = xgp[base];
        float c1 = xgp[base + 1*(2*DINNER)];
        float c2 = xgp[base + 2*(2*DINNER)];
        float c3 = xgp[base + 3*(2*DINNER)];
        float v0 = w4.x*p3 + w4.y*p2 + w4.z*p1 + w4.w*c0 + cb;
        float v1 = w4.x*p2 + w4.y*p1 + w4.z*c0 + w4.w*c1 + cb;
        float v2 = w4.x*p1 + w4.y*c0 + w4.z*c1 + w4.w*c2 + cb;
        float v3 = w4.x*c0 + w4.y*c1 + w4.z*c2 + w4.w*c3 + cb;
        float s0 = v0 / (1.f + __expf(-v0));
        float s1 = v1 / (1.f + __expf(-v1));
        float s2 = v2 / (1.f + __expf(-v2));
        float s3 = v3 / (1.f + __expf(-v3));
        size_t ob = ((size_t)(b*LSEQ + l))*DINNER + d;
        g_xs[ob           ] = s0;
        g_xs[ob + 1*DINNER] = s1;
        g_xs[ob + 2*DINNER] = s2;
        g_xs[ob + 3*DINNER] = s3;
        g_xs_bf[ob           ] = __float2bfloat16_rn(s0);
        g_xs_bf[ob + 1*DINNER] = __float2bfloat16_rn(s1);
        g_xs_bf[ob + 2*DINNER] = __float2bfloat16_rn(s2);
        g_xs_bf[ob + 3*DINNER] = __float2bfloat16_rn(s3);
        p3 = c1; p2 = c2; p1 = c3;
    }
}

/* ------------------------------------------------------------------ */
/* Bx + dA: 8 rows per block (one warp per row).                      */
/* ------------------------------------------------------------------ */
__global__ void bxda_kernel(const float* __restrict__ B_mat,
                            const float* __restrict__ A_log)
{
    int row  = blockIdx.x*8 + (threadIdx.x >> 5);
    int lane = threadIdx.x & 31;

    float sums[NSTATE];
    #pragma unroll
    for (int n = 0; n < NSTATE; n++) sums[n] = 0.f;

    const float* xr = g_xs + (size_t)row*DINNER;
    for (int d = lane; d < DINNER; d += 32) {
        float xv = xr[d];
        #pragma unroll
        for (int n = 0; n < NSTATE; n++)
            sums[n] += xv * B_mat[n*DINNER + d];
    }
    #pragma unroll
    for (int n = 0; n < NSTATE; n++)
        #pragma unroll
        for (int o = 16; o; o >>= 1)
            sums[n] += __shfl_xor_sync(0xffffffffu, sums[n], o);

    if (lane < NSTATE) {
        float delta = g_delta[row] * (1.0f/DINNER);
        float An    = -__expf(A_log[lane]);
        g_Bx[row*NSTATE + lane] = sums[lane] * delta;
        g_dA[row*NSTATE + lane] = __expf(delta * An);
    }
}

/* ------------------------------------------------------------------ */
/* Parallel scan (Hillis-Steele over affine maps)                     */
/* ------------------------------------------------------------------ */
__global__ __launch_bounds__(1024)
void scan_kernel()
{
    __shared__ float Aa[2][LSEQ];
    __shared__ float Bb[2][LSEQ];
    int bn = blockIdx.x;
    int b  = bn >> 4;
    int n  = bn & 15;
    int tid = threadIdx.x;

    for (int l = tid; l < LSEQ; l += 1024) {
        size_t idx = ((size_t)(b*LSEQ + l))*NSTATE + n;
        Aa[0][l] = g_dA[idx];
        Bb[0][l] = g_Bx[idx];
    }
    __syncthreads();
    int src = 0;
    for (int off = 1; off < LSEQ; off <<= 1) {
        int dst = src ^ 1;
        for (int l = tid; l < LSEQ; l += 1024) {
            float a = Aa[src][l], bv = Bb[src][l];
            if (l >= off) {
                float ap = Aa[src][l-off], bp = Bb[src][l-off];
                Aa[dst][l] = a * ap;
                Bb[dst][l] = a * bp + bv;
            } else {
                Aa[dst][l] = a;
                Bb[dst][l] = bv;
            }
        }
        __syncthreads();
        src ^= 1;
    }
    for (int l = tid; l < LSEQ; l += 1024) {
        size_t idx = ((size_t)(b*LSEQ + l))*NSTATE + n;
        g_hs[idx] = Bb[src][l];
    }
}

/* ------------------------------------------------------------------ */
/* y = (hs @ C^T + D*xs) * silu(gate), writes bf16                    */
/* ------------------------------------------------------------------ */
__global__ void ymix_kernel(const float* __restrict__ C_mat,
                            const float* __restrict__ D_vec)
{
    int row = blockIdx.x;
    int tx  = threadIdx.x;      /* 256 */
    __shared__ float hrow[NSTATE];
    if (tx < NSTATE) hrow[tx] = g_hs[row*NSTATE + tx];
    __syncthreads();

    for (int d = tx; d < DINNER; d += 256) {
        const float4* c4 = (const float4*)(C_mat + (size_t)d*NSTATE);
        float acc = 0.f;
        #pragma unroll
        for (int qq = 0; qq < 4; qq++) {
            float4 c = c4[qq];
            acc += c.x*hrow[qq*4+0] + c.y*hrow[qq*4+1]
                 + c.z*hrow[qq*4+2] + c.w*hrow[qq*4+3];
        }
        float xv = g_xs[(size_t)row*DINNER + d];
        float gt = g_xg[(size_t)row*(2*DINNER) + DINNER + d];
        float sg = gt / (1.f + __expf(-gt));
        g_yb[(size_t)row*DINNER + d] =
            __float2bfloat16_rn((acc + D_vec[d]*xv) * sg);
    }
}

/* ------------------------------------------------------------------ */
extern "C" void kernel_launch(void* const* d_in, const int* in_sizes, int n_in,
                              void* d_out, int out_size)
{
    const float* x        = (const float*)d_in[0];
    const float* ln_gamma = (const float*)d_in[1];
    const float* ln_beta  = (const float*)d_in[2];
    const float* W_in     = (const float*)d_in[3];
    const float* conv_w   = (const float*)d_in[4];
    const float* conv_b   = (const float*)d_in[5];
    const float* A_log    = (const float*)d_in[6];
    const float* B_mat    = (const float*)d_in[7];
    const float* C_mat    = (const float*)d_in[8];
    const float* D_vec    = (const float*)d_in[9];
    const float* Wd       = (const float*)d_in[10];
    const float* bd       = (const float*)d_in[11];
    const float* W_out    = (const float*)d_in[12];
    float* out = (float*)d_out;

    float *p_xg, *p_delta;
    __nv_bfloat16 *p_hb, *p_xsbf, *p_yb, *p_wt;
    cudaGetSymbolAddress((void**)&p_hb,    g_hb);
    cudaGetSymbolAddress((void**)&p_xg,    g_xg);
    cudaGetSymbolAddress((void**)&p_xsbf,  g_xs_bf);
    cudaGetSymbolAddress((void**)&p_delta, g_delta);
    cudaGetSymbolAddress((void**)&p_yb,    g_yb);
    cudaGetSymbolAddress((void**)&p_wt,    g_wt);

    /* 1. LayerNorm (bf16 out) */
    ln_kernel<<<ROWS, 256>>>(x, ln_gamma, ln_beta);

    zero_delta_kernel<<<(ROWS+255)/256, 256>>>();

    /* 2. W_in^T (bf16), then xg = h @ W_in */
    transpose_bf16_kernel<<<dim3((2*DINNER)/32, DMODEL/32), dim3(32,8)>>>(
        W_in, p_wt, DMODEL, 2*DINNER);
    mm_gemm_kernel<0><<<dim3((2*DINNER)/128, ROWS/128), 256>>>(
        p_hb, p_wt, p_xg, ROWS, 2*DINNER, DMODEL, nullptr, nullptr, nullptr);

    /* 3. depthwise causal conv + SiLU */
    conv_silu_kernel<<<dim3(DINNER/256, LSEQ/CONV_CH, BSZ), 256>>>(conv_w, conv_b);

    /* 4. Wd^T, then delta row-sums = sum softplus(xs @ Wd + bd) */
    transpose_bf16_kernel<<<dim3(DINNER/32, DINNER/32), dim3(32,8)>>>(
        Wd, p_wt, DINNER, DINNER);
    mm_gemm_kernel<1><<<dim3(DINNER/128, ROWS/128), 256>>>(
        p_xsbf, p_wt, nullptr, ROWS, DINNER, DINNER, bd, p_delta, nullptr);

    /* 5. Bx, dA */
    bxda_kernel<<<ROWS/8, 256>>>(B_mat, A_log);

    /* 6. scan over L */
    scan_kernel<<<BSZ*NSTATE, 1024>>>();

    /* 7. y = (hs @ C^T + D*xs) * silu(gate)  (bf16 out) */
    ymix_kernel<<<ROWS, 256>>>(C_mat, D_vec);

    /* 8. W_out^T, then out = y @ W_out + x */
    transpose_bf16_kernel<<<dim3(DMODEL/32, DINNER/32), dim3(32,8)>>>(
        W_out, p_wt, DINNER, DMODEL);
    mm_gemm_kernel<2><<<dim3(DMODEL/128, ROWS/128), 256>>>(
        p_yb, p_wt, out, ROWS, DMODEL, DINNER, nullptr, nullptr, x);
}